// round 16
// baseline (speedup 1.0000x reference)
#include <cuda_runtime.h>
#include <cuda_fp16.h>
#include <cstdint>

#define BB 8
#define CC 256
#define TT 16000
#define NN 32
#define NCH 32
#define LCH 500

typedef unsigned long long u64;

__device__ __half g_y[BB*CC*TT];
__device__ __half g_b[BB*CC*TT];
__device__ __half g_wa[512*256];
__device__ float2 g_w [CC*NN];
__device__ float2 g_w2[CC*NN];
__device__ float2 g_w3[CC*NN];
__device__ float2 g_w4[CC*NN];
__device__ float2 g_c2 [CC*NN];
__device__ float2 g_c2b[CC*NN];
__device__ float2 g_wL[CC*NN];
__device__ float  g_sig[CC];
__device__ float2 g_state[BB*CC*NCH*NN];

__device__ __forceinline__ u64 pk2(float lo, float hi){ u64 r; asm("mov.b64 %0,{%1,%2};":"=l"(r):"f"(lo),"f"(hi)); return r; }
__device__ __forceinline__ void up2(u64 v, float& lo, float& hi){ asm("mov.b64 {%0,%1},%2;":"=f"(lo),"=f"(hi):"l"(v)); }
__device__ __forceinline__ u64 f2fma(u64 a,u64 b,u64 c){ u64 d; asm("fma.rn.f32x2 %0,%1,%2,%3;":"=l"(d):"l"(a),"l"(b),"l"(c)); return d; }
__device__ __forceinline__ u64 f2mul(u64 a,u64 b){ u64 d; asm("mul.rn.f32x2 %0,%1,%2;":"=l"(d):"l"(a),"l"(b)); return d; }

__device__ __forceinline__ float geluf(float v){
    return 0.5f * v * (1.0f + erff(v * 0.7071067811865476f));
}

// ---------------- mma.sync helpers ----------------
__device__ __forceinline__ uint32_t smem_u32(const void* p){
    uint32_t a; asm("{ .reg .u64 t; cvta.to.shared.u64 t, %1; cvt.u32.u64 %0, t; }":"=r"(a):"l"(p)); return a;
}
__device__ __forceinline__ void ldm4(uint32_t* r, uint32_t addr){
    asm volatile("ldmatrix.sync.aligned.m8n8.x4.shared.b16 {%0,%1,%2,%3}, [%4];"
        :"=r"(r[0]),"=r"(r[1]),"=r"(r[2]),"=r"(r[3]):"r"(addr));
}
__device__ __forceinline__ void ldm4t(uint32_t* r, uint32_t addr){
    asm volatile("ldmatrix.sync.aligned.m8n8.x4.trans.shared.b16 {%0,%1,%2,%3}, [%4];"
        :"=r"(r[0]),"=r"(r[1]),"=r"(r[2]),"=r"(r[3]):"r"(addr));
}
__device__ __forceinline__ void mma_f16(float* c, const uint32_t* a, const uint32_t* b){
    asm volatile("mma.sync.aligned.m16n8k16.row.col.f32.f16.f16.f32 "
        "{%0,%1,%2,%3}, {%4,%5,%6,%7}, {%8,%9}, {%0,%1,%2,%3};"
        : "+f"(c[0]),"+f"(c[1]),"+f"(c[2]),"+f"(c[3])
        : "r"(a[0]),"r"(a[1]),"r"(a[2]),"r"(a[3]), "r"(b[0]),"r"(b[1]));
}
__device__ __forceinline__ void cpa(uint32_t dst, const void* src){
    asm volatile("cp.async.cg.shared.global [%0], [%1], 16;"::"r"(dst),"l"(src):"memory");
}
__device__ __forceinline__ void cp_commit(){ asm volatile("cp.async.commit_group;":::"memory"); }
__device__ __forceinline__ void cp_wait0(){ asm volatile("cp.async.wait_group 0;":::"memory"); }
__device__ __forceinline__ void cp_wait1(){ asm volatile("cp.async.wait_group 1;":::"memory"); }
__device__ __forceinline__ void cp_wait2(){ asm volatile("cp.async.wait_group 2;":::"memory"); }
__device__ __forceinline__ void cp_wait3(){ asm volatile("cp.async.wait_group 3;":::"memory"); }

// ---------- S4D parameter precompute ----------
__global__ void k_setup(const float* __restrict__ log_dt, const float* __restrict__ log_A_real,
                        const float* __restrict__ A_imag, const float* __restrict__ C_re,
                        const float* __restrict__ C_im){
    int i = blockIdx.x*256 + threadIdx.x;       // 8192
    int c = i >> 5;
    float dt = expf(log_dt[c]);
    float Ar = -expf(log_A_real[i]);
    float Ai = A_imag[i];
    float ar = dt*Ar, ai = dt*Ai;
    double dar = (double)ar, dai = (double)ai;
    float2 wk[5];
#pragma unroll
    for (int k = 1; k <= 4; k++){
        double s, cn; sincos(k*dai, &s, &cn);
        double e = exp(k*dar);
        wk[k] = make_float2((float)(e*cn), (float)(e*s));
    }
    {
        double s, cn; sincos((double)LCH*dai, &s, &cn);
        double e = exp((double)LCH*dar);
        g_wL[i] = make_float2((float)(e*cn), (float)(e*s));
    }
    float wr = wk[1].x, wi = wk[1].y;
    float Er = wr - 1.0f, Ei = wi;
    float den = Ar*Ar + Ai*Ai;
    float qr = (Er*Ar + Ei*Ai)/den;
    float qi = (Ei*Ar - Er*Ai)/den;
    float cr = C_re[i], ci = C_im[i];
    float2 c2 = make_float2(2.0f*(cr*qr - ci*qi), 2.0f*(cr*qi + ci*qr));
    g_w [i] = wk[1];
    g_w2[i] = wk[2];
    g_w3[i] = wk[3];
    g_w4[i] = wk[4];
    g_c2[i] = c2;
    g_c2b[i] = make_float2(c2.x*wr - c2.y*wi, c2.x*wi + c2.y*wr);
    float sg = c2.x;
#pragma unroll
    for (int o=16;o;o>>=1) sg += __shfl_xor_sync(0xffffffffu, sg, o);
    if ((i & 31) == 0) g_sig[c] = sg;
}

// ---------- W -> fp16 ----------
__global__ void k_wh(const float* __restrict__ W){
    int i = blockIdx.x*256 + threadIdx.x;
    g_wa[i] = __float2half_rn(W[i]);
}

// ---------- channel-wise LayerNorm (over C) + PReLU, fp16 out ----------
__global__ void k_ln(const float* __restrict__ x, const float* __restrict__ gamma,
                     const float* __restrict__ beta, const float* __restrict__ pw){
    __shared__ float tile[256*33];
    __shared__ float mu[32];
    __shared__ float rs[32];
    int b = blockIdx.y;
    int t0 = blockIdx.x*32;
    int c = threadIdx.x;
    const float* xp = x + ((size_t)(b*CC + c))*TT + t0;
#pragma unroll
    for (int j=0;j<8;j++){
        float4 v = *(const float4*)(xp + j*4);
        tile[c*33 + j*4+0]=v.x; tile[c*33 + j*4+1]=v.y;
        tile[c*33 + j*4+2]=v.z; tile[c*33 + j*4+3]=v.w;
    }
    __syncthreads();
    int w = c>>5, lane = c&31;
#pragma unroll
    for (int q=0;q<4;q++){
        int t = w*4+q;
        float s=0.f, s2=0.f;
#pragma unroll
        for (int m=0;m<8;m++){ float v = tile[(lane+32*m)*33 + t]; s += v; s2 = fmaf(v,v,s2); }
#pragma unroll
        for (int o=16;o;o>>=1){ s += __shfl_xor_sync(0xffffffffu,s,o); s2 += __shfl_xor_sync(0xffffffffu,s2,o); }
        if (lane==0){
            float m  = s*(1.0f/CC);
            float var = fmaxf(s2*(1.0f/CC) - m*m, 0.0f);
            mu[t]=m; rs[t]=rsqrtf(var + 1e-8f);
        }
    }
    __syncthreads();
    float ga = gamma[c], be = beta[c], pc = pw[c];
    __half* yp = g_y + ((size_t)(b*CC + c))*TT + t0;
#pragma unroll
    for (int j=0;j<8;j++){
        float os[4];
#pragma unroll
        for (int e=0;e<4;e++){
            int t = j*4+e;
            float v = (tile[c*33 + t]-mu[t])*rs[t]*ga + be;
            os[e] = (v >= 0.0f) ? v : pc*v;
        }
        __half2 h0 = __floats2half2_rn(os[0], os[1]);
        __half2 h1 = __floats2half2_rn(os[2], os[3]);
        *(uint2*)(yp + j*4) = make_uint2(*(uint32_t*)&h0, *(uint32_t*)&h1);
    }
}

// ---------- scan phase 1: chunk-local end states, 4-step unrolled (plain loads) ----------
__global__ void __launch_bounds__(256) k_scan1(){
    int tid = blockIdx.x*256 + threadIdx.x;
    int u   = tid >> 2;
    int sub = tid & 3;
    int ch = u & (NCH-1), c = (u>>5) & 255, b = u >> 13;
    int nb = sub*8;
    int cb = c*NN + nb;
    u64 w4r[4], w4i[4], nw4i[4], w3r[4], w3i[4], w2r[4], w2i[4], w1r[4], w1i[4];
    u64 hr[4], hi[4];
#pragma unroll
    for (int p=0;p<4;p++){
        float2 a, bq;
        a = g_w4[cb+2*p]; bq = g_w4[cb+2*p+1];
        w4r[p]=pk2(a.x,bq.x); w4i[p]=pk2(a.y,bq.y); nw4i[p]=pk2(-a.y,-bq.y);
        a = g_w3[cb+2*p]; bq = g_w3[cb+2*p+1];
        w3r[p]=pk2(a.x,bq.x); w3i[p]=pk2(a.y,bq.y);
        a = g_w2[cb+2*p]; bq = g_w2[cb+2*p+1];
        w2r[p]=pk2(a.x,bq.x); w2i[p]=pk2(a.y,bq.y);
        a = g_w[cb+2*p];  bq = g_w[cb+2*p+1];
        w1r[p]=pk2(a.x,bq.x); w1i[p]=pk2(a.y,bq.y);
        hr[p]=0ull; hi[p]=0ull;
    }
    const __half* yp = g_y + ((size_t)(b*CC + c))*TT + ch*LCH;
    for (int i=0;i<LCH;i+=4){
        uint2 raw = *(const uint2*)(yp + i);
        float2 f01 = __half22float2(*(__half2*)&raw.x);
        float2 f23 = __half22float2(*(__half2*)&raw.y);
        u64 y0 = pk2(f01.x,f01.x), y1 = pk2(f01.y,f01.y);
        u64 y2 = pk2(f23.x,f23.x), y3 = pk2(f23.y,f23.y);
#pragma unroll
        for (int p=0;p<4;p++){
            u64 ur = f2fma(w3r[p], y0, f2fma(w2r[p], y1, f2fma(w1r[p], y2, y3)));
            u64 ui = f2fma(w3i[p], y0, f2fma(w2i[p], y1, f2mul(w1i[p], y2)));
            u64 t1  = f2fma(w4r[p], hr[p], ur);
            u64 nhr = f2fma(nw4i[p], hi[p], t1);
            u64 t2  = f2fma(w4i[p], hr[p], ui);
            hi[p]   = f2fma(w4r[p], hi[p], t2);
            hr[p]   = nhr;
        }
    }
    float2* sp = g_state + (((size_t)(b*CC + c))*NCH + ch)*NN + nb;
#pragma unroll
    for (int p=0;p<4;p++){
        float r0,r1,i0,i1; up2(hr[p],r0,r1); up2(hi[p],i0,i1);
        *(float4*)(sp + 2*p) = make_float4(r0,i0,r1,i1);
    }
}

// ---------- scan phase 2: exclusive prefix across chunks ----------
__global__ void k_comb(){
    int tid = blockIdx.x*256 + threadIdx.x;
    int n = tid & 31, c = (tid>>5) & 255, b = tid >> 13;
    float2 wL = g_wL[c*NN + n];
    float2* sp = g_state + ((size_t)(b*CC + c))*NCH*NN + n;
    float Hr=0.f, Hi=0.f;
#pragma unroll
    for (int j=0;j<NCH;j++){
        float2 he = sp[(size_t)j*NN];
        sp[(size_t)j*NN] = make_float2(Hr, Hi);
        float nHr = wL.x*Hr - wL.y*Hi + he.x;
        float nHi = wL.x*Hi + wL.y*Hr + he.y;
        Hr = nHr; Hi = nHi;
    }
}

// ---------- scan phase 3: 2-step emit (dual dot), fp16 out, y prefetch ----------
__global__ void __launch_bounds__(256) k_scan2(const float* __restrict__ D){
    int tid = blockIdx.x*256 + threadIdx.x;
    int u   = tid >> 2;
    int sub = tid & 3;
    int ch = u & (NCH-1), c = (u>>5) & 255, b = u >> 13;
    int nb = sub*8;
    int cb = c*NN + nb;
    u64 w2r[4], w2i[4], nw2i[4], w1r[4], w1i[4];
    u64 cAr[4], cAn[4], cBr[4], cBn[4];
    u64 hr[4], hi[4];
    const float2* sp = g_state + (((size_t)(b*CC + c))*NCH + ch)*NN + nb;
#pragma unroll
    for (int p=0;p<4;p++){
        float2 a, bq;
        a = g_w2[cb+2*p]; bq = g_w2[cb+2*p+1];
        w2r[p]=pk2(a.x,bq.x); w2i[p]=pk2(a.y,bq.y); nw2i[p]=pk2(-a.y,-bq.y);
        a = g_w[cb+2*p];  bq = g_w[cb+2*p+1];
        w1r[p]=pk2(a.x,bq.x); w1i[p]=pk2(a.y,bq.y);
        a = g_c2b[cb+2*p]; bq = g_c2b[cb+2*p+1];
        cAr[p]=pk2(a.x,bq.x); cAn[p]=pk2(-a.y,-bq.y);
        a = g_c2[cb+2*p];  bq = g_c2[cb+2*p+1];
        cBr[p]=pk2(a.x,bq.x); cBn[p]=pk2(-a.y,-bq.y);
        float4 st = *(const float4*)(sp + 2*p);
        hr[p]=pk2(st.x,st.z); hi[p]=pk2(st.y,st.w);
    }
    float Dv = D[c];
    float sD = g_sig[c] + Dv;
    size_t base = ((size_t)(b*CC + c))*TT + ch*LCH;
    const __half* yp = g_y + base;
    uint2 raw = *(const uint2*)(yp);
    for (int i=0;i<LCH;i+=4){
        uint2 cur = raw;
        if (i + 4 < LCH) raw = *(const uint2*)(yp + i + 4);
        float2 f01 = __half22float2(*(__half2*)&cur.x);
        float2 f23 = __half22float2(*(__half2*)&cur.y);
        float ys[4] = {f01.x, f01.y, f23.x, f23.y};
        float sv[4];
#pragma unroll
        for (int g=0; g<2; g++){
            float y1 = ys[2*g], y2 = ys[2*g+1];
            u64 y1p = pk2(y1,y1), y2p = pk2(y2,y2);
            u64 accA = f2mul(cAr[0], hr[0]);
            accA = f2fma(cAn[0], hi[0], accA);
#pragma unroll
            for (int p=1;p<4;p++){
                accA = f2fma(cAr[p], hr[p], accA);
                accA = f2fma(cAn[p], hi[p], accA);
            }
#pragma unroll
            for (int p=0;p<4;p++){
                u64 ur = f2fma(w1r[p], y1p, y2p);
                u64 ui = f2mul(w1i[p], y1p);
                u64 t1  = f2fma(w2r[p], hr[p], ur);
                u64 nhr = f2fma(nw2i[p], hi[p], t1);
                u64 t2  = f2fma(w2i[p], hr[p], ui);
                hi[p]   = f2fma(w2r[p], hi[p], t2);
                hr[p]   = nhr;
            }
            u64 accB = f2mul(cBr[0], hr[0]);
            accB = f2fma(cBn[0], hi[0], accB);
#pragma unroll
            for (int p=1;p<4;p++){
                accB = f2fma(cBr[p], hr[p], accB);
                accB = f2fma(cBn[p], hi[p], accB);
            }
            float al, ah; up2(accA, al, ah);
            float pA = al + ah;
            float bl_, bh_; up2(accB, bl_, bh_);
            float pB = bl_ + bh_;
            pA += __shfl_xor_sync(0xffffffffu, pA, 1);
            pA += __shfl_xor_sync(0xffffffffu, pA, 2);
            pB += __shfl_xor_sync(0xffffffffu, pB, 1);
            pB += __shfl_xor_sync(0xffffffffu, pB, 2);
            sv[2*g]   = pA + sD*y1;
            sv[2*g+1] = pB + Dv*y2;
        }
        if (sub == 0){
            __half2 a01 = __floats2half2_rn(geluf(sv[0]), geluf(sv[1]));
            __half2 a23 = __floats2half2_rn(geluf(sv[2]), geluf(sv[3]));
            *(uint2*)(g_b + base + i) = make_uint2(*(uint32_t*)&a01, *(uint32_t*)&a23);
        }
    }
}

// ==================== persistent-A fp16 GEMM, 5-tile continuous pipeline ====================
// A (256 rows GLU-interleaved x 256 k) resident in smem, loaded once per CTA.
// B-only 5-stage cp.async ring runs continuously across 5 t-tiles (40 chunks).
// Epilogue register-local (no smem use) so the ring never stalls.
#define A_STR 528
#define B_BASE 135168
#define B_STR 272
#define B_STG 8704
#define SM_TOT (B_BASE + 5*B_STG)
#define NTILE 5

__global__ void __launch_bounds__(512) k_gemm(const float* __restrict__ x,
                                              const float* __restrict__ b_out,
                                              float* __restrict__ out){
    extern __shared__ char smem[];
    uint32_t sbase = smem_u32(smem);
    int tid = threadIdx.x;
    int lane = tid & 31, wid = tid >> 5;
    int wm = wid >> 2, wn = wid & 3;
    int c0 = blockIdx.x * 128;
    int b  = blockIdx.z;
    int tbase = blockIdx.y * NTILE;

    // A gather with GLU interleave, resident (loaded once)
    int ar  = tid >> 1;
    int blk = ar >> 4, r16 = ar & 15;
    int agr = c0 + blk*8 + (r16 & 7) + ((r16 & 8) ? 256 : 0);
    {
        uint32_t adst = sbase + (uint32_t)ar*A_STR;
        const __half* wsrc = g_wa + agr*256;
        int s0 = (tid & 1)*16;
#pragma unroll
        for (int s = 0; s < 16; s++)
            cpa(adst + (uint32_t)(s0+s)*16, wsrc + (s0+s)*8);
    }

    int brow = tid >> 4, bchk = tid & 15;

#define LOAD_B(g) do{ \
    int t0_ = (tbase + (g)/8)*128; \
    int k0_ = ((g)&7)*32; \
    uint32_t bh = sbase + B_BASE + (uint32_t)((g)%5)*B_STG + (uint32_t)brow*B_STR + (uint32_t)bchk*16; \
    const __half* bsh = g_b + ((size_t)(b*CC + k0_ + brow))*TT + t0_ + bchk*8; \
    cpa(bh, bsh); \
}while(0)

    LOAD_B(0); cp_commit();        // group 0 = A + B0
    LOAD_B(1); cp_commit();
    LOAD_B(2); cp_commit();
    LOAD_B(3); cp_commit();

    uint32_t a_row = (uint32_t)(wm*64 + (lane & 15));
    uint32_t a_cb  = (uint32_t)((lane >> 4) * 16);
    int g2 = lane >> 3;
    uint32_t b_krow = (uint32_t)((g2 & 1)*8 + (lane & 7));
    uint32_t b_colb = (uint32_t)((wn*32 + (g2 >> 1)*8) * 2);
    int qr = lane >> 2, qc = (lane & 3)*2;

    for (int tile = 0; tile < NTILE; tile++){
        float acc[4][4][4];
#pragma unroll
        for (int i=0;i<4;i++)
#pragma unroll
            for (int j=0;j<4;j++)
#pragma unroll
                for (int e=0;e<4;e++) acc[i][j][e]=0.f;

        for (int kt = 0; kt < 8; kt++){
            int g = tile*8 + kt;
            if (g <= 36) cp_wait3();
            else if (g == 37) cp_wait2();
            else if (g == 38) cp_wait1();
            else cp_wait0();
            __syncthreads();
            if (g < 36){ LOAD_B(g+4); cp_commit(); }
            uint32_t bstb = sbase + B_BASE + (uint32_t)(g%5)*B_STG;

#pragma unroll
            for (int k16 = 0; k16 < 2; k16++){
                uint32_t Bh[2][4], Aa[4][4];
                uint32_t brow_s = (uint32_t)(k16*16) + b_krow;
#pragma unroll
                for (int nb = 0; nb < 2; nb++)
                    ldm4t(Bh[nb], bstb + brow_s*B_STR + b_colb + (uint32_t)(nb*32));
                uint32_t acb = (uint32_t)(kt*64 + k16*32) + a_cb;
#pragma unroll
                for (int mb = 0; mb < 4; mb++)
                    ldm4(Aa[mb], sbase + (a_row + mb*16)*A_STR + acb);
#pragma unroll
                for (int mb = 0; mb < 4; mb++)
#pragma unroll
                    for (int j = 0; j < 4; j++)
                        mma_f16(acc[mb][j], Aa[mb], &Bh[j>>1][(j&1)*2]);
            }
        }

        // -------- register-local epilogue: GLU + sigmoid + residual --------
        int t0 = (tbase + tile)*128;
#pragma unroll
        for (int mb = 0; mb < 4; mb++){
            int chn = c0 + (wm*4 + mb)*8 + qr;
            float bt = b_out[chn];
            float bb = b_out[256 + chn];
            const float* xp = x   + ((size_t)(b*CC + chn))*TT + t0;
            float*       op = out + ((size_t)(b*CC + chn))*TT + t0;
#pragma unroll
            for (int j = 0; j < 4; j++){
                int col = wn*32 + j*8 + qc;
                float2 xv = *(const float2*)(xp + col);
                float sa = 1.0f/(1.0f + expf(-(acc[mb][j][2] + bb)));
                float sb = 1.0f/(1.0f + expf(-(acc[mb][j][3] + bb)));
                float2 o;
                o.x = xv.x + (acc[mb][j][0] + bt) * sa;
                o.y = xv.y + (acc[mb][j][1] + bt) * sb;
                *(float2*)(op + col) = o;
            }
        }
    }
}

extern "C" void kernel_launch(void* const* d_in, const int* in_sizes, int n_in,
                              void* d_out, int out_size) {
    const float* x        = (const float*)d_in[0];
    const float* gamma    = (const float*)d_in[1];
    const float* beta     = (const float*)d_in[2];
    const float* prelu_w  = (const float*)d_in[3];
    const float* log_dt   = (const float*)d_in[4];
    const float* log_A    = (const float*)d_in[5];
    const float* A_imag   = (const float*)d_in[6];
    const float* C_re     = (const float*)d_in[7];
    const float* C_im     = (const float*)d_in[8];
    const float* D        = (const float*)d_in[9];
    const float* W_out    = (const float*)d_in[10];
    const float* b_out    = (const float*)d_in[11];
    float* out = (float*)d_out;

    cudaFuncSetAttribute(k_gemm, cudaFuncAttributeMaxDynamicSharedMemorySize, SM_TOT);

    k_setup<<<32, 256>>>(log_dt, log_A, A_imag, C_re, C_im);
    k_wh<<<512, 256>>>(W_out);
    k_ln<<<dim3(TT/32, BB), 256>>>(x, gamma, beta, prelu_w);
    k_scan1<<<(BB*CC*NCH*4)/256, 256>>>();
    k_comb<<<(BB*CC*NN)/256, 256>>>();
    k_scan2<<<(BB*CC*NCH*4)/256, 256>>>(D);
    k_gemm<<<dim3(2, 25, BB), 512, SM_TOT>>>(x, b_out, out);
}

// round 17
// speedup vs baseline: 1.1209x; 1.1209x over previous
#include <cuda_runtime.h>
#include <cuda_fp16.h>
#include <cstdint>

#define BB 8
#define CC 256
#define TT 16000
#define NN 32
#define NCH 32
#define LCH 500

typedef unsigned long long u64;

__device__ __half g_y[BB*CC*TT];
__device__ __half g_b[BB*CC*TT];
__device__ __half g_wa[512*256];
__device__ float2 g_w [CC*NN];
__device__ float2 g_w2[CC*NN];
__device__ float2 g_w3[CC*NN];
__device__ float2 g_w4[CC*NN];
__device__ float2 g_c2 [CC*NN];
__device__ float2 g_c2b[CC*NN];
__device__ float2 g_wL[CC*NN];
__device__ float  g_sig[CC];
__device__ float2 g_state[BB*CC*NCH*NN];

__device__ __forceinline__ u64 pk2(float lo, float hi){ u64 r; asm("mov.b64 %0,{%1,%2};":"=l"(r):"f"(lo),"f"(hi)); return r; }
__device__ __forceinline__ void up2(u64 v, float& lo, float& hi){ asm("mov.b64 {%0,%1},%2;":"=f"(lo),"=f"(hi):"l"(v)); }
__device__ __forceinline__ u64 f2fma(u64 a,u64 b,u64 c){ u64 d; asm("fma.rn.f32x2 %0,%1,%2,%3;":"=l"(d):"l"(a),"l"(b),"l"(c)); return d; }
__device__ __forceinline__ u64 f2mul(u64 a,u64 b){ u64 d; asm("mul.rn.f32x2 %0,%1,%2;":"=l"(d):"l"(a),"l"(b)); return d; }

__device__ __forceinline__ float geluf(float v){
    return 0.5f * v * (1.0f + erff(v * 0.7071067811865476f));
}

// ---------------- mma.sync helpers ----------------
__device__ __forceinline__ uint32_t smem_u32(const void* p){
    uint32_t a; asm("{ .reg .u64 t; cvta.to.shared.u64 t, %1; cvt.u32.u64 %0, t; }":"=r"(a):"l"(p)); return a;
}
__device__ __forceinline__ void ldm4(uint32_t* r, uint32_t addr){
    asm volatile("ldmatrix.sync.aligned.m8n8.x4.shared.b16 {%0,%1,%2,%3}, [%4];"
        :"=r"(r[0]),"=r"(r[1]),"=r"(r[2]),"=r"(r[3]):"r"(addr));
}
__device__ __forceinline__ void ldm4t(uint32_t* r, uint32_t addr){
    asm volatile("ldmatrix.sync.aligned.m8n8.x4.trans.shared.b16 {%0,%1,%2,%3}, [%4];"
        :"=r"(r[0]),"=r"(r[1]),"=r"(r[2]),"=r"(r[3]):"r"(addr));
}
__device__ __forceinline__ void mma_f16(float* c, const uint32_t* a, const uint32_t* b){
    asm volatile("mma.sync.aligned.m16n8k16.row.col.f32.f16.f16.f32 "
        "{%0,%1,%2,%3}, {%4,%5,%6,%7}, {%8,%9}, {%0,%1,%2,%3};"
        : "+f"(c[0]),"+f"(c[1]),"+f"(c[2]),"+f"(c[3])
        : "r"(a[0]),"r"(a[1]),"r"(a[2]),"r"(a[3]), "r"(b[0]),"r"(b[1]));
}
__device__ __forceinline__ void cpa(uint32_t dst, const void* src){
    asm volatile("cp.async.cg.shared.global [%0], [%1], 16;"::"r"(dst),"l"(src):"memory");
}
__device__ __forceinline__ void cp_commit(){ asm volatile("cp.async.commit_group;":::"memory"); }
__device__ __forceinline__ void cp_wait0(){ asm volatile("cp.async.wait_group 0;":::"memory"); }
__device__ __forceinline__ void cp_wait1(){ asm volatile("cp.async.wait_group 1;":::"memory"); }
__device__ __forceinline__ void cp_wait2(){ asm volatile("cp.async.wait_group 2;":::"memory"); }
__device__ __forceinline__ void cp_wait3(){ asm volatile("cp.async.wait_group 3;":::"memory"); }

// ---------- S4D parameter precompute ----------
__global__ void k_setup(const float* __restrict__ log_dt, const float* __restrict__ log_A_real,
                        const float* __restrict__ A_imag, const float* __restrict__ C_re,
                        const float* __restrict__ C_im){
    int i = blockIdx.x*256 + threadIdx.x;       // 8192
    int c = i >> 5;
    float dt = expf(log_dt[c]);
    float Ar = -expf(log_A_real[i]);
    float Ai = A_imag[i];
    float ar = dt*Ar, ai = dt*Ai;
    double dar = (double)ar, dai = (double)ai;
    float2 wk[5];
#pragma unroll
    for (int k = 1; k <= 4; k++){
        double s, cn; sincos(k*dai, &s, &cn);
        double e = exp(k*dar);
        wk[k] = make_float2((float)(e*cn), (float)(e*s));
    }
    {
        double s, cn; sincos((double)LCH*dai, &s, &cn);
        double e = exp((double)LCH*dar);
        g_wL[i] = make_float2((float)(e*cn), (float)(e*s));
    }
    float wr = wk[1].x, wi = wk[1].y;
    float Er = wr - 1.0f, Ei = wi;
    float den = Ar*Ar + Ai*Ai;
    float qr = (Er*Ar + Ei*Ai)/den;
    float qi = (Ei*Ar - Er*Ai)/den;
    float cr = C_re[i], ci = C_im[i];
    float2 c2 = make_float2(2.0f*(cr*qr - ci*qi), 2.0f*(cr*qi + ci*qr));
    g_w [i] = wk[1];
    g_w2[i] = wk[2];
    g_w3[i] = wk[3];
    g_w4[i] = wk[4];
    g_c2[i] = c2;
    g_c2b[i] = make_float2(c2.x*wr - c2.y*wi, c2.x*wi + c2.y*wr);
    float sg = c2.x;
#pragma unroll
    for (int o=16;o;o>>=1) sg += __shfl_xor_sync(0xffffffffu, sg, o);
    if ((i & 31) == 0) g_sig[c] = sg;
}

// ---------- W -> fp16 ----------
__global__ void k_wh(const float* __restrict__ W){
    int i = blockIdx.x*256 + threadIdx.x;
    g_wa[i] = __float2half_rn(W[i]);
}

// ---------- channel-wise LayerNorm (over C) + PReLU, fully coalesced ----------
__global__ void k_ln(const float* __restrict__ x, const float* __restrict__ gamma,
                     const float* __restrict__ beta, const float* __restrict__ pw){
    __shared__ float tile[256*33];
    __shared__ float mu[32];
    __shared__ float rs[32];
    int b = blockIdx.y;
    int t0 = blockIdx.x*32;
    int tid = threadIdx.x;
    int w = tid>>5, lane = tid&31;
    // load: warp w loads rows [w*32, w*32+32), each row 32 floats coalesced (128B)
    const float* xb = x + ((size_t)b*CC)*TT + t0;
#pragma unroll
    for (int r=0;r<32;r++){
        int row = w*32 + r;
        tile[row*33 + lane] = xb[(size_t)row*TT + lane];
    }
    __syncthreads();
    // stats: warp w computes timesteps t = w*4 .. w*4+3
#pragma unroll
    for (int q=0;q<4;q++){
        int t = w*4+q;
        float s=0.f, s2=0.f;
#pragma unroll
        for (int m=0;m<8;m++){ float v = tile[(lane+32*m)*33 + t]; s += v; s2 = fmaf(v,v,s2); }
#pragma unroll
        for (int o=16;o;o>>=1){ s += __shfl_xor_sync(0xffffffffu,s,o); s2 += __shfl_xor_sync(0xffffffffu,s2,o); }
        if (lane==0){
            float m  = s*(1.0f/CC);
            float var = fmaxf(s2*(1.0f/CC) - m*m, 0.0f);
            mu[t]=m; rs[t]=rsqrtf(var + 1e-8f);
        }
    }
    __syncthreads();
    // output: warp w writes rows [w*32, w*32+32), each row 32 halves coalesced (64B)
    __half* yb = g_y + ((size_t)b*CC)*TT + t0;
    float m_ = mu[lane], r_ = rs[lane];
#pragma unroll
    for (int r=0;r<32;r++){
        int row = w*32 + r;
        float ga = gamma[row], be = beta[row], pc = pw[row];
        float v = (tile[row*33 + lane] - m_)*r_*ga + be;
        v = (v >= 0.0f) ? v : pc*v;
        yb[(size_t)row*TT + lane] = __float2half_rn(v);
    }
}

// ---------- scan phase 1: chunk-local end states, 4-step unrolled (plain loads) ----------
__global__ void __launch_bounds__(256) k_scan1(){
    int tid = blockIdx.x*256 + threadIdx.x;
    int u   = tid >> 2;
    int sub = tid & 3;
    int ch = u & (NCH-1), c = (u>>5) & 255, b = u >> 13;
    int nb = sub*8;
    int cb = c*NN + nb;
    u64 w4r[4], w4i[4], nw4i[4], w3r[4], w3i[4], w2r[4], w2i[4], w1r[4], w1i[4];
    u64 hr[4], hi[4];
#pragma unroll
    for (int p=0;p<4;p++){
        float2 a, bq;
        a = g_w4[cb+2*p]; bq = g_w4[cb+2*p+1];
        w4r[p]=pk2(a.x,bq.x); w4i[p]=pk2(a.y,bq.y); nw4i[p]=pk2(-a.y,-bq.y);
        a = g_w3[cb+2*p]; bq = g_w3[cb+2*p+1];
        w3r[p]=pk2(a.x,bq.x); w3i[p]=pk2(a.y,bq.y);
        a = g_w2[cb+2*p]; bq = g_w2[cb+2*p+1];
        w2r[p]=pk2(a.x,bq.x); w2i[p]=pk2(a.y,bq.y);
        a = g_w[cb+2*p];  bq = g_w[cb+2*p+1];
        w1r[p]=pk2(a.x,bq.x); w1i[p]=pk2(a.y,bq.y);
        hr[p]=0ull; hi[p]=0ull;
    }
    const __half* yp = g_y + ((size_t)(b*CC + c))*TT + ch*LCH;
    for (int i=0;i<LCH;i+=4){
        uint2 raw = *(const uint2*)(yp + i);
        float2 f01 = __half22float2(*(__half2*)&raw.x);
        float2 f23 = __half22float2(*(__half2*)&raw.y);
        u64 y0 = pk2(f01.x,f01.x), y1 = pk2(f01.y,f01.y);
        u64 y2 = pk2(f23.x,f23.x), y3 = pk2(f23.y,f23.y);
#pragma unroll
        for (int p=0;p<4;p++){
            u64 ur = f2fma(w3r[p], y0, f2fma(w2r[p], y1, f2fma(w1r[p], y2, y3)));
            u64 ui = f2fma(w3i[p], y0, f2fma(w2i[p], y1, f2mul(w1i[p], y2)));
            u64 t1  = f2fma(w4r[p], hr[p], ur);
            u64 nhr = f2fma(nw4i[p], hi[p], t1);
            u64 t2  = f2fma(w4i[p], hr[p], ui);
            hi[p]   = f2fma(w4r[p], hi[p], t2);
            hr[p]   = nhr;
        }
    }
    float2* sp = g_state + (((size_t)(b*CC + c))*NCH + ch)*NN + nb;
#pragma unroll
    for (int p=0;p<4;p++){
        float r0,r1,i0,i1; up2(hr[p],r0,r1); up2(hi[p],i0,i1);
        *(float4*)(sp + 2*p) = make_float4(r0,i0,r1,i1);
    }
}

// ---------- scan phase 2: exclusive prefix across chunks ----------
__global__ void k_comb(){
    int tid = blockIdx.x*256 + threadIdx.x;
    int n = tid & 31, c = (tid>>5) & 255, b = tid >> 13;
    float2 wL = g_wL[c*NN + n];
    float2* sp = g_state + ((size_t)(b*CC + c))*NCH*NN + n;
    float Hr=0.f, Hi=0.f;
#pragma unroll
    for (int j=0;j<NCH;j++){
        float2 he = sp[(size_t)j*NN];
        sp[(size_t)j*NN] = make_float2(Hr, Hi);
        float nHr = wL.x*Hr - wL.y*Hi + he.x;
        float nHi = wL.x*Hi + wL.y*Hr + he.y;
        Hr = nHr; Hi = nHi;
    }
}

// ---------- scan phase 3: 2-step emit (dual dot), fp16 out, y prefetch ----------
__global__ void __launch_bounds__(256) k_scan2(const float* __restrict__ D){
    int tid = blockIdx.x*256 + threadIdx.x;
    int u   = tid >> 2;
    int sub = tid & 3;
    int ch = u & (NCH-1), c = (u>>5) & 255, b = u >> 13;
    int nb = sub*8;
    int cb = c*NN + nb;
    u64 w2r[4], w2i[4], nw2i[4], w1r[4], w1i[4];
    u64 cAr[4], cAn[4], cBr[4], cBn[4];
    u64 hr[4], hi[4];
    const float2* sp = g_state + (((size_t)(b*CC + c))*NCH + ch)*NN + nb;
#pragma unroll
    for (int p=0;p<4;p++){
        float2 a, bq;
        a = g_w2[cb+2*p]; bq = g_w2[cb+2*p+1];
        w2r[p]=pk2(a.x,bq.x); w2i[p]=pk2(a.y,bq.y); nw2i[p]=pk2(-a.y,-bq.y);
        a = g_w[cb+2*p];  bq = g_w[cb+2*p+1];
        w1r[p]=pk2(a.x,bq.x); w1i[p]=pk2(a.y,bq.y);
        a = g_c2b[cb+2*p]; bq = g_c2b[cb+2*p+1];
        cAr[p]=pk2(a.x,bq.x); cAn[p]=pk2(-a.y,-bq.y);
        a = g_c2[cb+2*p];  bq = g_c2[cb+2*p+1];
        cBr[p]=pk2(a.x,bq.x); cBn[p]=pk2(-a.y,-bq.y);
        float4 st = *(const float4*)(sp + 2*p);
        hr[p]=pk2(st.x,st.z); hi[p]=pk2(st.y,st.w);
    }
    float Dv = D[c];
    float sD = g_sig[c] + Dv;
    size_t base = ((size_t)(b*CC + c))*TT + ch*LCH;
    const __half* yp = g_y + base;
    uint2 raw = *(const uint2*)(yp);
    for (int i=0;i<LCH;i+=4){
        uint2 cur = raw;
        if (i + 4 < LCH) raw = *(const uint2*)(yp + i + 4);
        float2 f01 = __half22float2(*(__half2*)&cur.x);
        float2 f23 = __half22float2(*(__half2*)&cur.y);
        float ys[4] = {f01.x, f01.y, f23.x, f23.y};
        float sv[4];
#pragma unroll
        for (int g=0; g<2; g++){
            float y1 = ys[2*g], y2 = ys[2*g+1];
            u64 y1p = pk2(y1,y1), y2p = pk2(y2,y2);
            u64 accA = f2mul(cAr[0], hr[0]);
            accA = f2fma(cAn[0], hi[0], accA);
#pragma unroll
            for (int p=1;p<4;p++){
                accA = f2fma(cAr[p], hr[p], accA);
                accA = f2fma(cAn[p], hi[p], accA);
            }
#pragma unroll
            for (int p=0;p<4;p++){
                u64 ur = f2fma(w1r[p], y1p, y2p);
                u64 ui = f2mul(w1i[p], y1p);
                u64 t1  = f2fma(w2r[p], hr[p], ur);
                u64 nhr = f2fma(nw2i[p], hi[p], t1);
                u64 t2  = f2fma(w2i[p], hr[p], ui);
                hi[p]   = f2fma(w2r[p], hi[p], t2);
                hr[p]   = nhr;
            }
            u64 accB = f2mul(cBr[0], hr[0]);
            accB = f2fma(cBn[0], hi[0], accB);
#pragma unroll
            for (int p=1;p<4;p++){
                accB = f2fma(cBr[p], hr[p], accB);
                accB = f2fma(cBn[p], hi[p], accB);
            }
            float al, ah; up2(accA, al, ah);
            float pA = al + ah;
            float bl_, bh_; up2(accB, bl_, bh_);
            float pB = bl_ + bh_;
            pA += __shfl_xor_sync(0xffffffffu, pA, 1);
            pA += __shfl_xor_sync(0xffffffffu, pA, 2);
            pB += __shfl_xor_sync(0xffffffffu, pB, 1);
            pB += __shfl_xor_sync(0xffffffffu, pB, 2);
            sv[2*g]   = pA + sD*y1;
            sv[2*g+1] = pB + Dv*y2;
        }
        if (sub == 0){
            __half2 a01 = __floats2half2_rn(geluf(sv[0]), geluf(sv[1]));
            __half2 a23 = __floats2half2_rn(geluf(sv[2]), geluf(sv[3]));
            *(uint2*)(g_b + base + i) = make_uint2(*(uint32_t*)&a01, *(uint32_t*)&a23);
        }
    }
}

// ==================== fp16 GEMM, 5-stage pipeline, register-local GLU epilogue (R15) ====================
#define A_STR 80
#define B_STR 272
#define ST_A  20480
#define ST_SZ 29184
#define SM_TOT (5*ST_SZ)

__global__ void __launch_bounds__(512) k_gemm(const float* __restrict__ x,
                                              const float* __restrict__ b_out,
                                              float* __restrict__ out){
    extern __shared__ char smem[];
    uint32_t sbase = smem_u32(smem);
    int tid = threadIdx.x;
    int lane = tid & 31, wid = tid >> 5;
    int wm = wid >> 2, wn = wid & 3;
    int c0 = blockIdx.x * 128;
    int t0 = blockIdx.y * 128;
    int b  = blockIdx.z;

    float acc[4][4][4];
#pragma unroll
    for (int i=0;i<4;i++)
#pragma unroll
        for (int j=0;j<4;j++)
#pragma unroll
            for (int e=0;e<4;e++) acc[i][j][e]=0.f;

    // A gather with GLU interleave
    int ar  = tid >> 1;
    int asg = (tid & 1)*2;
    int blk = ar >> 4, r16 = ar & 15;
    int agr = c0 + blk*8 + (r16 & 7) + ((r16 & 8) ? 256 : 0);
    int brow = tid >> 4, bchk = tid & 15;
    size_t bsrc_row = ((size_t)(b*CC + brow))*TT + t0 + bchk*8;

#define LOAD_CHUNK(kt, st) do{ \
    int k0 = (kt)*32; \
    uint32_t stb = sbase + (uint32_t)(st)*ST_SZ; \
    uint32_t ah = stb + (uint32_t)ar*A_STR; \
    const __half* wsh = g_wa + agr*256 + k0; \
    cpa(ah + (asg+0)*16, wsh + (asg+0)*8); \
    cpa(ah + (asg+1)*16, wsh + (asg+1)*8); \
    uint32_t bh = stb + ST_A + (uint32_t)brow*B_STR + (uint32_t)bchk*16; \
    const __half* bsh = g_b + bsrc_row + (size_t)k0*TT; \
    cpa(bh, bsh); \
}while(0)

    LOAD_CHUNK(0, 0); cp_commit();
    LOAD_CHUNK(1, 1); cp_commit();
    LOAD_CHUNK(2, 2); cp_commit();
    LOAD_CHUNK(3, 3); cp_commit();

    uint32_t a_row = (uint32_t)(wm*64 + (lane & 15));
    uint32_t a_cb  = (uint32_t)((lane >> 4) * 16);
    int g2 = lane >> 3;
    uint32_t b_krow = (uint32_t)((g2 & 1)*8 + (lane & 7));
    uint32_t b_colb = (uint32_t)((wn*32 + (g2 >> 1)*8) * 2);

    for (int kt = 0; kt < 8; kt++){
        if (kt < 5) cp_wait3();
        else if (kt == 5) cp_wait2();
        else if (kt == 6) cp_wait1();
        else cp_wait0();
        __syncthreads();
        if (kt < 4){ LOAD_CHUNK(kt+4, (kt+4)%5); cp_commit(); }
        uint32_t stb = sbase + (uint32_t)(kt%5)*ST_SZ;

#pragma unroll
        for (int k16 = 0; k16 < 2; k16++){
            uint32_t Bh[2][4], Aa[4][4];
            uint32_t brow_s = (uint32_t)(k16*16) + b_krow;
#pragma unroll
            for (int nb = 0; nb < 2; nb++)
                ldm4t(Bh[nb], stb + ST_A + brow_s*B_STR + b_colb + (uint32_t)(nb*32));
            uint32_t acb = (uint32_t)(k16*32) + a_cb;
#pragma unroll
            for (int mb = 0; mb < 4; mb++)
                ldm4(Aa[mb], stb + (a_row + mb*16)*A_STR + acb);
#pragma unroll
            for (int mb = 0; mb < 4; mb++)
#pragma unroll
                for (int j = 0; j < 4; j++)
                    mma_f16(acc[mb][j], Aa[mb], &Bh[j>>1][(j&1)*2]);
        }
    }

    // -------- register-local epilogue: GLU + sigmoid + residual --------
    int qr = lane >> 2, qc = (lane & 3)*2;
#pragma unroll
    for (int mb = 0; mb < 4; mb++){
        int chn = c0 + (wm*4 + mb)*8 + qr;
        float bt = b_out[chn];
        float bb = b_out[256 + chn];
        const float* xp = x   + ((size_t)(b*CC + chn))*TT + t0;
        float*       op = out + ((size_t)(b*CC + chn))*TT + t0;
#pragma unroll
        for (int j = 0; j < 4; j++){
            int col = wn*32 + j*8 + qc;
            float2 xv = *(const float2*)(xp + col);
            float sa = 1.0f/(1.0f + expf(-(acc[mb][j][2] + bb)));
            float sb = 1.0f/(1.0f + expf(-(acc[mb][j][3] + bb)));
            float2 o;
            o.x = xv.x + (acc[mb][j][0] + bt) * sa;
            o.y = xv.y + (acc[mb][j][1] + bt) * sb;
            *(float2*)(op + col) = o;
        }
    }
}

extern "C" void kernel_launch(void* const* d_in, const int* in_sizes, int n_in,
                              void* d_out, int out_size) {
    const float* x        = (const float*)d_in[0];
    const float* gamma    = (const float*)d_in[1];
    const float* beta     = (const float*)d_in[2];
    const float* prelu_w  = (const float*)d_in[3];
    const float* log_dt   = (const float*)d_in[4];
    const float* log_A    = (const float*)d_in[5];
    const float* A_imag   = (const float*)d_in[6];
    const float* C_re     = (const float*)d_in[7];
    const float* C_im     = (const float*)d_in[8];
    const float* D        = (const float*)d_in[9];
    const float* W_out    = (const float*)d_in[10];
    const float* b_out    = (const float*)d_in[11];
    float* out = (float*)d_out;

    cudaFuncSetAttribute(k_gemm, cudaFuncAttributeMaxDynamicSharedMemorySize, SM_TOT);

    k_setup<<<32, 256>>>(log_dt, log_A, A_imag, C_re, C_im);
    k_wh<<<512, 256>>>(W_out);
    k_ln<<<dim3(TT/32, BB), 256>>>(x, gamma, beta, prelu_w);
    k_scan1<<<(BB*CC*NCH*4)/256, 256>>>();
    k_comb<<<(BB*CC*NN)/256, 256>>>();
    k_scan2<<<(BB*CC*NCH*4)/256, 256>>>(D);
    k_gemm<<<dim3(2, 125, BB), 512, SM_TOT>>>(x, b_out, out);
}